// round 17
// baseline (speedup 1.0000x reference)
#include <cuda_runtime.h>
#include <cuda_bf16.h>

#define O_    4
#define N_    3072
#define NSPL  2
#define LSPL  (N_ / NSPL)    // 1536 candidates per split
#define KNN   10
#define TOLC  0.01f
#define FMAXV 3.402823466e+38f
#define BTHR  128            // threads per knn block (1 query/thread)
#define CAP   112            // per-thread insert buffer (mean ~54, ~8 sigma)
#define FULLM 0xFFFFFFFFu

// ---------------- device scratch (no allocations allowed) ----------------
__device__ float4 g_pip4[O_ * N_];                 // (x, y, z, |p|^2)
__device__ float4 g_nrm4[O_ * N_];                 // raw normal
__device__ unsigned long long g_part[O_ * 3][NSPL][KNN][N_];  // sorted partial keys
__device__ float  g_scr[O_][3][N_];                // per-pair signed distance

// ordered-float helpers
__device__ __forceinline__ unsigned f2ord(float f) {
    unsigned b = __float_as_uint(f);
    return b ^ ((unsigned)(((int)b) >> 31) | 0x80000000u);
}
__device__ __forceinline__ float ord2f(unsigned u) {
    int ib = (u & 0x80000000u) ? (int)(u ^ 0x80000000u) : ~(int)u;
    return __int_as_float(ib);
}

// ---------------- kernel 1: prep + transform fused ----------------
__global__ void transform_kernel(const float* __restrict__ points,
                                 const float* __restrict__ T_obj,
                                 const float* __restrict__ T_plane) {
    int i = blockIdx.x * blockDim.x + threadIdx.x;
    if (i >= O_ * N_) return;
    int o = i / N_;

    float Rp[9], tp[3];
    #pragma unroll
    for (int r = 0; r < 3; r++) {
        #pragma unroll
        for (int c = 0; c < 3; c++) Rp[r * 3 + c] = __ldg(&T_plane[r * 4 + c]);
        tp[r] = __ldg(&T_plane[r * 4 + 3]);
    }
    const float* To = T_obj + o * 16;
    // inv(T_plane) rigid: [Rp^T | -Rp^T tp]
    float R[3][3], tr[3];
    #pragma unroll
    for (int r = 0; r < 3; r++) {
        R[r][0] = Rp[0 + r] * To[0] + Rp[3 + r] * To[4] + Rp[6 + r] * To[8];
        R[r][1] = Rp[0 + r] * To[1] + Rp[3 + r] * To[5] + Rp[6 + r] * To[9];
        R[r][2] = Rp[0 + r] * To[2] + Rp[3 + r] * To[6] + Rp[6 + r] * To[10];
        tr[r]   = Rp[0 + r] * (To[3] - tp[0]) + Rp[3 + r] * (To[7] - tp[1])
                + Rp[6 + r] * (To[11] - tp[2]);
    }

    const float* p = points + (size_t)i * 6;
    float x = p[0], y = p[1], z = p[2];
    float px = fmaf(R[0][0], x, fmaf(R[0][1], y, fmaf(R[0][2], z, tr[0])));
    float py = fmaf(R[1][0], x, fmaf(R[1][1], y, fmaf(R[1][2], z, tr[1])));
    float pz = fmaf(R[2][0], x, fmaf(R[2][1], y, fmaf(R[2][2], z, tr[2])));
    float rr = px * px + py * py + pz * pz;
    g_pip4[i] = make_float4(px, py, pz, rr);
    g_nrm4[i] = make_float4(p[3], p[4], p[5], 0.f);
}

// ---------------- kernel 2: pair-min bitmask partial top-10 over one split ----------------
// blockIdx = (query chunk, pair, split); smem: LSPL float4 (24K) + buf u16 (28K)
__global__ void __launch_bounds__(BTHR) knn_partial_kernel() {
    extern __shared__ float4 sh[];                      // LSPL candidates
    unsigned short* buf = (unsigned short*)(sh + LSPL); // buf[slot*BTHR + tid]
    int pair = blockIdx.y;
    int spl  = blockIdx.z;
    int b  = pair / 3;
    int oi = pair - b * 3;
    int o  = oi + (oi >= b ? 1 : 0);
    int tid = threadIdx.x;
    int n  = blockIdx.x * BTHR + tid;
    int jbase = spl * LSPL;

    const float4* cand = g_pip4 + o * N_ + jbase;
    for (int i = tid; i < LSPL; i += BTHR) sh[i] = cand[i];
    __syncthreads();

    float4 q = g_pip4[b * N_ + n];
    float m2x = -2.f * q.x, m2y = -2.f * q.y, m2z = -2.f * q.z;

    float a[KNN];
    #pragma unroll
    for (int s = 0; s < KNN; s++) a[s] = FMAXV;
    float thresh = FMAXV;
    int cnt = 0;

    #define DIST(c) fmaf((c).x, m2x, fmaf((c).y, m2y, fmaf((c).z, m2z, (c).w)))
    #define INSERT(idv, dv)                                     \
        do { int _slot = cnt < CAP - 1 ? cnt : CAP - 1;         \
             buf[_slot * BTHR + tid] = (unsigned short)(idv);   \
             cnt++;                                             \
             float _t = (dv);                                   \
             _Pragma("unroll")                                  \
             for (int _s = 0; _s < KNN; _s++) {                 \
                 float _lo = fminf(a[_s], _t);                  \
                 _t = fmaxf(a[_s], _t);                         \
                 a[_s] = _lo;                                   \
             }                                                  \
             thresh = a[KNN - 1]; } while (0)

    // ---- scan: 64 candidates (32 pairs) per chunk; pair-min mask; recheck replay ----
    #pragma unroll 1
    for (int j0 = 0; j0 < LSPL; j0 += 64) {
        unsigned mask = 0u;
        #pragma unroll
        for (int u = 0; u < 32; u++) {
            float4 c0 = sh[j0 + 2 * u];
            float4 c1 = sh[j0 + 2 * u + 1];
            float d0 = DIST(c0);
            float d1 = DIST(c1);
            mask |= (fminf(d0, d1) < thresh) ? (1u << u) : 0u;
        }
        #pragma unroll 1
        while (__any_sync(FULLM, mask != 0u)) {
            if (mask) {
                int bit = __ffs(mask) - 1;
                mask &= mask - 1u;
                int id0 = j0 + 2 * bit;
                float4 c0 = sh[id0];
                float d0 = DIST(c0);
                if (d0 < thresh) INSERT(id0, d0);
                float4 c1 = sh[id0 + 1];
                float d1 = DIST(c1);
                if (d1 < thresh) INSERT(id0 + 1, d1);
            }
        }
    }
    // a[0..9] is the EXACT split top-10: any candidate beating the final
    // threshold had pair-min < scan-time threshold (monotone) -> replayed.

    // ---- id selection: first 10 buffered (ascending local id) with d <= a[9] ----
    unsigned ids[KNN];
    int w = 0;
    if (cnt < CAP) {
        #pragma unroll 1
        for (int t = 0; t < cnt && w < KNN; t++) {
            unsigned id = buf[t * BTHR + tid];
            float4 c = sh[id];
            float d = DIST(c);
            if (d <= thresh) ids[w++] = id;
        }
    } else {
        // overflow fallback (P ~ 1e-10/thread): exact rescan ascending
        #pragma unroll 1
        for (int j = 0; j < LSPL && w < KNN; j++) {
            float4 c = sh[j];
            float d = DIST(c);
            if (d <= thresh) ids[w++] = (unsigned)j;
        }
    }
    while (w < KNN) ids[w++] = ids[0];   // safety (unreachable: LSPL >= KNN)

    // ---- build sorted u64 keys (ord(d)<<32 | global id) ----
    unsigned long long k[KNN];
    #pragma unroll
    for (int s = 0; s < KNN; s++) k[s] = 0xFFFFFFFFFFFFFFFFull;
    #pragma unroll
    for (int t = 0; t < KNN; t++) {
        unsigned id = ids[t];
        float4 c = sh[id];
        float d = DIST(c);
        unsigned long long key =
            ((unsigned long long)f2ord(d) << 32) | (unsigned)(jbase + id);
        #pragma unroll
        for (int s = 0; s < KNN; s++) {
            unsigned long long lo = (k[s] < key) ? k[s] : key;
            key = (k[s] < key) ? key : k[s];
            k[s] = lo;
        }
    }
    #pragma unroll
    for (int s = 0; s < KNN; s++) g_part[pair][spl][s][n] = k[s];

    #undef INSERT
    #undef DIST
}

// ---------------- kernel 3: per-pair merge + votes (1 thread per (b,oi,n)) ----------------
__global__ void merge_kernel() {
    int i = blockIdx.x * blockDim.x + threadIdx.x;
    if (i >= O_ * 3 * N_) return;
    int pair = i / N_;
    int n = i - pair * N_;
    int b = pair / 3;
    int oi = pair - b * 3;
    int o = oi + (oi >= b ? 1 : 0);
    float4 q = g_pip4[b * N_ + n];

    unsigned long long A[KNN], B[KNN], K[KNN];
    #pragma unroll
    for (int s = 0; s < KNN; s++) {
        A[s] = g_part[pair][0][s][n];
        B[s] = g_part[pair][1][s][n];
    }
    // shift-register merge: 10 smallest of A ∪ B (ties: smaller global id wins)
    #pragma unroll
    for (int s = 0; s < KNN; s++) {
        bool ta = A[0] <= B[0];
        K[s] = ta ? A[0] : B[0];
        #pragma unroll
        for (int t = 0; t < KNN - 1; t++) {
            unsigned long long an = A[t + 1], bn = B[t + 1];
            A[t] = ta ? an : A[t];
            B[t] = ta ? B[t] : bn;
        }
        if (ta) A[KNN - 1] = 0xFFFFFFFFFFFFFFFFull;
        else    B[KNN - 1] = 0xFFFFFFFFFFFFFFFFull;
    }
    int votes = 0;
    const float4* pp = g_pip4 + o * N_;
    const float4* nr = g_nrm4 + o * N_;
    #pragma unroll
    for (int s = 0; s < KNN; s++) {
        unsigned id = (unsigned)(K[s] & 0xFFFFFFFFu);
        float4 c  = __ldg(&pp[id]);
        float4 nm = __ldg(&nr[id]);
        float dt = (c.x - q.x) * nm.x + (c.y - q.y) * nm.y + (c.z - q.z) * nm.z;
        votes += (dt > 0.f) ? 1 : 0;
    }
    float dmin = ord2f((unsigned)(K[0] >> 32));
    float D = q.w + dmin;
    float d0 = sqrtf(fmaxf(D, 0.f));
    g_scr[b][oi][n] = (votes > 8) ? -d0 : d0;   // sum(insides) > 0.8*k -> >= 9
}

// ---------------- kernel 4: min over other objects + plane, write out ----------------
__global__ void finalize_kernel(float* __restrict__ out, int out_size) {
    int i = blockIdx.x * blockDim.x + threadIdx.x;
    if (i >= O_ * N_) return;
    int b = i / N_;
    int n = i % N_;
    float sd = g_pip4[i].z;                 // plane signed distance = pip.z
    sd = fminf(sd, g_scr[b][0][n]);
    sd = fminf(sd, g_scr[b][1][n]);
    sd = fminf(sd, g_scr[b][2][n]);
    out[i] = sd;
    if (out_size >= 2 * O_ * N_)
        out[O_ * N_ + i] = (sd < -TOLC) ? 1.0f : 0.0f;
}

// ---------------- launch ----------------
extern "C" void kernel_launch(void* const* d_in, const int* in_sizes, int n_in,
                              void* d_out, int out_size) {
    const float* points  = nullptr;
    const float* T_obj   = nullptr;
    const float* T_plane = nullptr;
    for (int i = 0; i < n_in; i++) {
        if (in_sizes[i] == O_ * N_ * 6) points  = (const float*)d_in[i];
        else if (in_sizes[i] == 64)     T_obj   = (const float*)d_in[i];
        else if (in_sizes[i] == 16)     T_plane = (const float*)d_in[i];
    }

    transform_kernel<<<(O_ * N_ + 255) / 256, 256>>>(points, T_obj, T_plane);

    int smem = LSPL * (int)sizeof(float4) + CAP * BTHR * (int)sizeof(unsigned short);
    (void)cudaFuncSetAttribute(knn_partial_kernel,
                               cudaFuncAttributeMaxDynamicSharedMemorySize, smem);
    knn_partial_kernel<<<dim3(N_ / BTHR, O_ * 3, NSPL), BTHR, smem>>>();

    merge_kernel<<<(O_ * 3 * N_ + 127) / 128, 128>>>();
    finalize_kernel<<<(O_ * N_ + 255) / 256, 256>>>((float*)d_out, out_size);
}